// round 1
// baseline (speedup 1.0000x reference)
#include <cuda_runtime.h>
#include <math.h>

// LSTM cell: gates[B,4H] = x@Wx^T + bx + h@Wh^T + bh ; then pointwise.
// B=8192, I=H=1024, 4H=4096, K_total = I+H = 2048.
//
// Kernel 1: TF32 mma.sync tiled GEMM (128x128x32 CTA tile, 8 warps of 64x32),
//           concatenated-K over (x|h) x (Wx|Wh)^T, writes fp32 gates scratch.
// Kernel 2: fused bias + sigmoid/tanh + c/h epilogue (memory bound).

#define B_DIM 8192
#define H_DIM 1024
#define GATES_N 4096
#define K_TOTAL 2048
#define BM 128
#define BN 128
#define BK 32
#define PADK 36   // smem row stride (floats) -> conflict-free fragment loads

__device__ float g_gates[(size_t)B_DIM * GATES_N];  // 134 MB scratch

__device__ __forceinline__ unsigned f2tf32(float f) {
    unsigned r;
    asm("cvt.rna.tf32.f32 %0, %1;" : "=r"(r) : "f"(f));
    return r;
}

__global__ __launch_bounds__(256) void gemm_gates_kernel(
    const float* __restrict__ x,   // [B, I]
    const float* __restrict__ h,   // [B, H]
    const float* __restrict__ Wx,  // [4H, I]
    const float* __restrict__ Wh)  // [4H, H]
{
    __shared__ unsigned As[BM][PADK];  // tf32 bits, [m][k]
    __shared__ unsigned Bs[BN][PADK];  // tf32 bits, [n][k]

    const int tid  = threadIdx.x;
    const int warp = tid >> 5;
    const int lane = tid & 31;
    const int wm = (warp >> 2) * 64;   // warp m-offset in CTA tile (0,64)
    const int wn = (warp & 3) * 32;    // warp n-offset (0,32,64,96)
    const int bm = blockIdx.y * BM;
    const int bn = blockIdx.x * BN;

    // global->reg staging: each thread loads 4 float4 from A and 4 from B per tile
    const int lr = tid >> 3;          // 0..31 (row group)
    const int lc = (tid & 7) * 4;     // 0,4,...,28 (col within BK)

    float acc[4][4][4];
#pragma unroll
    for (int i = 0; i < 4; i++)
#pragma unroll
        for (int j = 0; j < 4; j++)
#pragma unroll
            for (int r = 0; r < 4; r++) acc[i][j][r] = 0.f;

    float4 ra[4], rb[4];
    // prologue: k-tile 0 comes from x / Wx
#pragma unroll
    for (int p = 0; p < 4; p++) {
        int row = lr + p * 32;
        ra[p] = *(const float4*)(x  + (size_t)(bm + row) * 1024 + lc);
        rb[p] = *(const float4*)(Wx + (size_t)(bn + row) * 1024 + lc);
    }

    const int NT = K_TOTAL / BK;  // 64
    for (int kt = 0; kt < NT; ++kt) {
        // store staged tile to smem (convert to tf32 with round-to-nearest)
#pragma unroll
        for (int p = 0; p < 4; p++) {
            int row = lr + p * 32;
            As[row][lc + 0] = f2tf32(ra[p].x);
            As[row][lc + 1] = f2tf32(ra[p].y);
            As[row][lc + 2] = f2tf32(ra[p].z);
            As[row][lc + 3] = f2tf32(ra[p].w);
            Bs[row][lc + 0] = f2tf32(rb[p].x);
            Bs[row][lc + 1] = f2tf32(rb[p].y);
            Bs[row][lc + 2] = f2tf32(rb[p].z);
            Bs[row][lc + 3] = f2tf32(rb[p].w);
        }
        __syncthreads();

        // prefetch next k-tile into registers (source switches at k=1024)
        if (kt + 1 < NT) {
            int k0 = (kt + 1) * BK;
            const float* An = (k0 < 1024) ? x : h;
            const float* Bn = (k0 < 1024) ? Wx : Wh;
            int kc = (k0 < 1024) ? k0 : (k0 - 1024);
#pragma unroll
            for (int p = 0; p < 4; p++) {
                int row = lr + p * 32;
                ra[p] = *(const float4*)(An + (size_t)(bm + row) * 1024 + kc + lc);
                rb[p] = *(const float4*)(Bn + (size_t)(bn + row) * 1024 + kc + lc);
            }
        }

        // compute: 4 k-steps of 8
#pragma unroll
        for (int ks = 0; ks < 4; ++ks) {
            const int kb = ks * 8;
            unsigned af[4][4], bf[4][2];
#pragma unroll
            for (int i = 0; i < 4; i++) {
                int r0 = wm + i * 16 + (lane >> 2);
                int c0 = kb + (lane & 3);
                af[i][0] = As[r0][c0];
                af[i][1] = As[r0 + 8][c0];
                af[i][2] = As[r0][c0 + 4];
                af[i][3] = As[r0 + 8][c0 + 4];
            }
#pragma unroll
            for (int j = 0; j < 4; j++) {
                int n0 = wn + j * 8 + (lane >> 2);
                int c0 = kb + (lane & 3);
                bf[j][0] = Bs[n0][c0];
                bf[j][1] = Bs[n0][c0 + 4];
            }
#pragma unroll
            for (int i = 0; i < 4; i++)
#pragma unroll
                for (int j = 0; j < 4; j++) {
                    asm volatile(
                        "mma.sync.aligned.m16n8k8.row.col.f32.tf32.tf32.f32 "
                        "{%0,%1,%2,%3}, {%4,%5,%6,%7}, {%8,%9}, {%0,%1,%2,%3};"
                        : "+f"(acc[i][j][0]), "+f"(acc[i][j][1]),
                          "+f"(acc[i][j][2]), "+f"(acc[i][j][3])
                        : "r"(af[i][0]), "r"(af[i][1]), "r"(af[i][2]), "r"(af[i][3]),
                          "r"(bf[j][0]), "r"(bf[j][1]));
                }
        }
        __syncthreads();
    }

    // epilogue: write gates (fp32) to scratch
#pragma unroll
    for (int i = 0; i < 4; i++) {
        int r0 = bm + wm + i * 16 + (lane >> 2);
#pragma unroll
        for (int j = 0; j < 4; j++) {
            int c0 = bn + wn + j * 8 + 2 * (lane & 3);
            *(float2*)(g_gates + (size_t)r0 * GATES_N + c0) =
                make_float2(acc[i][j][0], acc[i][j][1]);
            *(float2*)(g_gates + (size_t)(r0 + 8) * GATES_N + c0) =
                make_float2(acc[i][j][2], acc[i][j][3]);
        }
    }
}

__device__ __forceinline__ float sigmoidf_(float v) {
    return 1.0f / (1.0f + expf(-v));
}

__global__ __launch_bounds__(256) void lstm_pointwise_kernel(
    const float* __restrict__ c_prev,  // [B, H]
    const float* __restrict__ bx,      // [4H]
    const float* __restrict__ bh,      // [4H]
    float* __restrict__ out)           // [2*B*H]: c then h
{
    int idx = blockIdx.x * blockDim.x + threadIdx.x;  // over B*H/4
    int b  = idx >> 8;            // / (H/4)
    int cg = (idx & 255) * 4;     // col within H, float4 group

    size_t base = (size_t)b * GATES_N + cg;
    float4 ig = *(const float4*)(g_gates + base);
    float4 fg = *(const float4*)(g_gates + base + 1024);
    float4 og = *(const float4*)(g_gates + base + 2048);
    float4 gg = *(const float4*)(g_gates + base + 3072);

    float4 bxi = *(const float4*)(bx + cg);
    float4 bxf = *(const float4*)(bx + cg + 1024);
    float4 bxo = *(const float4*)(bx + cg + 2048);
    float4 bxg = *(const float4*)(bx + cg + 3072);
    float4 bhi = *(const float4*)(bh + cg);
    float4 bhf = *(const float4*)(bh + cg + 1024);
    float4 bho = *(const float4*)(bh + cg + 2048);
    float4 bhg = *(const float4*)(bh + cg + 3072);

    float4 cp = *(const float4*)(c_prev + (size_t)b * H_DIM + cg);

    float iv[4] = {ig.x + bxi.x + bhi.x, ig.y + bxi.y + bhi.y,
                   ig.z + bxi.z + bhi.z, ig.w + bxi.w + bhi.w};
    float fv[4] = {fg.x + bxf.x + bhf.x, fg.y + bxf.y + bhf.y,
                   fg.z + bxf.z + bhf.z, fg.w + bxf.w + bhf.w};
    float ov[4] = {og.x + bxo.x + bho.x, og.y + bxo.y + bho.y,
                   og.z + bxo.z + bho.z, og.w + bxo.w + bho.w};
    float gv[4] = {gg.x + bxg.x + bhg.x, gg.y + bxg.y + bhg.y,
                   gg.z + bxg.z + bhg.z, gg.w + bxg.w + bhg.w};
    float cpv[4] = {cp.x, cp.y, cp.z, cp.w};

    float cv[4], hv[4];
#pragma unroll
    for (int q = 0; q < 4; q++) {
        float i_g = sigmoidf_(iv[q]);
        float f_g = sigmoidf_(fv[q]);
        float o_g = sigmoidf_(ov[q]);
        float g_g = tanhf(gv[q]);
        cv[q] = f_g * cpv[q] + i_g * g_g;
        hv[q] = o_g * tanhf(cv[q]);
    }

    size_t obase = (size_t)b * H_DIM + cg;
    *(float4*)(out + obase) = make_float4(cv[0], cv[1], cv[2], cv[3]);
    *(float4*)(out + (size_t)B_DIM * H_DIM + obase) =
        make_float4(hv[0], hv[1], hv[2], hv[3]);
}

extern "C" void kernel_launch(void* const* d_in, const int* in_sizes, int n_in,
                              void* d_out, int out_size) {
    const float* x      = (const float*)d_in[0];  // [B, I]
    const float* c_prev = (const float*)d_in[1];  // [B, H]
    const float* h_prev = (const float*)d_in[2];  // [B, H]
    const float* Wx     = (const float*)d_in[3];  // [4H, I]
    const float* bx     = (const float*)d_in[4];  // [4H]
    const float* Wh     = (const float*)d_in[5];  // [4H, H]
    const float* bh     = (const float*)d_in[6];  // [4H]
    float* out = (float*)d_out;

    dim3 grid(GATES_N / BN, B_DIM / BM);  // (32, 64)
    gemm_gates_kernel<<<grid, 256>>>(x, h_prev, Wx, Wh);

    int n4 = (B_DIM * H_DIM) / 4;  // 2M threads
    lstm_pointwise_kernel<<<n4 / 256, 256>>>(c_prev, bx, bh, out);
}

// round 3
// speedup vs baseline: 1.0682x; 1.0682x over previous
#include <cuda_runtime.h>
#include <math.h>
#include <stdint.h>

// Fused LSTM cell, mma.sync tf32 path (compute_103-safe; tcgen05.ld is 'a'-only
// on this toolchain and unusable).
// gates[B,4H] = x@Wx^T + h@Wh^T (+bias in epilogue), pointwise fused.
// CTA tile: M=128 x N=256 (4 gates x 64 h-cols, gate-interleaved), BK=32.
// 3-stage cp.async pipeline; raw fp32 bits fed to tf32 mma (HW RZ truncation).

#define B_DIM 8192
#define H_DIM 1024
#define BM 128
#define BN 256
#define BK 32
#define PADK 36                    // floats per smem row (144B, 16B-aligned)
#define A_STAGE_BYTES (BM * PADK * 4)        // 18432
#define B_STAGE_BYTES (BN * PADK * 4)        // 36864
#define STAGE_BYTES   (A_STAGE_BYTES + B_STAGE_BYTES)  // 55296
#define STAGES 3
#define NSTG 64                    // 2048 / 32
#define SM_BIAS (STAGES * STAGE_BYTES)       // 165888
#define SMEM_TOTAL (SM_BIAS + 256 * 4)       // 166912

__device__ __forceinline__ uint32_t smem_u32(const void* p) {
    uint32_t a;
    asm("{ .reg .u64 t; cvta.to.shared.u64 t, %1; cvt.u32.u64 %0, t; }" : "=r"(a) : "l"(p));
    return a;
}
__device__ __forceinline__ void cp16(uint32_t dst, const void* src) {
    asm volatile("cp.async.cg.shared.global [%0], [%1], 16;" :: "r"(dst), "l"(src));
}

// stage kt into buffer kt%STAGES.
// B smem row r maps to weight row: gate=(r>>3)&3, hcol = c0 + (r>>5)*8 + (r&7)
__device__ __forceinline__ void load_stage(
    uint32_t sb, int kt, int m0, int c0, int tid,
    const float* __restrict__ x, const float* __restrict__ h,
    const float* __restrict__ Wx, const float* __restrict__ Wh)
{
    const int k0 = kt * BK;
    const float* Asrc = (k0 < 1024) ? x : h;
    const float* Bsrc = (k0 < 1024) ? Wx : Wh;
    const int kc = k0 & 1023;
    const uint32_t abase = sb + (kt % STAGES) * STAGE_BYTES;
    const uint32_t bbase = abase + A_STAGE_BYTES;
#pragma unroll
    for (int p = 0; p < 4; p++) {               // A: 128 rows x 8 chunks
        int ch = tid + p * 256;
        int row = ch >> 3, c16 = ch & 7;
        cp16(abase + row * (PADK * 4) + c16 * 16,
             Asrc + (size_t)(m0 + row) * 1024 + kc + c16 * 4);
    }
#pragma unroll
    for (int p = 0; p < 8; p++) {               // B: 256 rows x 8 chunks
        int ch = tid + p * 256;
        int row = ch >> 3, c16 = ch & 7;
        int wrow = ((row >> 3) & 3) * 1024 + c0 + (row >> 5) * 8 + (row & 7);
        cp16(bbase + row * (PADK * 4) + c16 * 16,
             Bsrc + (size_t)wrow * 1024 + kc + c16 * 4);
    }
}

__global__ void __launch_bounds__(256, 1) lstm_fused_kernel(
    const float* __restrict__ x,      // [B,1024]
    const float* __restrict__ c_prev, // [B,1024]
    const float* __restrict__ h_prev, // [B,1024]
    const float* __restrict__ Wx,     // [4096,1024]
    const float* __restrict__ bx,     // [4096]
    const float* __restrict__ Wh,     // [4096,1024]
    const float* __restrict__ bh,     // [4096]
    float* __restrict__ out)          // [2*B*1024]: c then h
{
    extern __shared__ char smem[];
    const uint32_t sb = smem_u32(smem);
    const int tid = threadIdx.x;
    const int warp = tid >> 5, lane = tid & 31;
    const int wm = (warp >> 2) * 64;       // 0,64
    const int wn = (warp & 3) * 64;        // 0,64,128,192 (smem B rows)
    const int m0 = blockIdx.y * BM;
    const int c0 = blockIdx.x * 64;        // 64 h-cols per CTA

    // bias sums: bs[g*64 + col]
    {
        int g = tid >> 6, col = tid & 63;
        ((float*)(smem + SM_BIAS))[tid] = bx[g * 1024 + c0 + col] + bh[g * 1024 + c0 + col];
    }

    float acc[4][8][4];
#pragma unroll
    for (int i = 0; i < 4; i++)
#pragma unroll
        for (int j = 0; j < 8; j++)
#pragma unroll
            for (int r = 0; r < 4; r++) acc[i][j][r] = 0.f;

    load_stage(sb, 0, m0, c0, tid, x, h_prev, Wx, Wh);
    asm volatile("cp.async.commit_group;" ::: "memory");
    load_stage(sb, 1, m0, c0, tid, x, h_prev, Wx, Wh);
    asm volatile("cp.async.commit_group;" ::: "memory");

    for (int kt = 0; kt < NSTG; ++kt) {
        if (kt + 2 < NSTG)
            load_stage(sb, kt + 2, m0, c0, tid, x, h_prev, Wx, Wh);
        asm volatile("cp.async.commit_group;" ::: "memory");
        asm volatile("cp.async.wait_group 2;" ::: "memory");
        __syncthreads();

        const uint32_t abuf = sb + (kt % STAGES) * STAGE_BYTES;
        const uint32_t bbuf = abuf + A_STAGE_BYTES;
        const unsigned* As = (const unsigned*)(smem + (abuf - sb));
        const unsigned* Bs = (const unsigned*)(smem + (bbuf - sb));

#pragma unroll
        for (int ks = 0; ks < 4; ++ks) {
            const int kb = ks * 8;
            const int cA = kb + (lane & 3);
            unsigned af[4][4], bf[8][2];
#pragma unroll
            for (int i = 0; i < 4; i++) {
                int r0 = wm + i * 16 + (lane >> 2);
                af[i][0] = As[r0 * PADK + cA];
                af[i][1] = As[(r0 + 8) * PADK + cA];
                af[i][2] = As[r0 * PADK + cA + 4];
                af[i][3] = As[(r0 + 8) * PADK + cA + 4];
            }
#pragma unroll
            for (int j = 0; j < 8; j++) {
                int n0 = wn + j * 8 + (lane >> 2);
                bf[j][0] = Bs[n0 * PADK + cA];
                bf[j][1] = Bs[n0 * PADK + cA + 4];
            }
#pragma unroll
            for (int i = 0; i < 4; i++)
#pragma unroll
                for (int j = 0; j < 8; j++) {
                    asm volatile(
                        "mma.sync.aligned.m16n8k8.row.col.f32.tf32.tf32.f32 "
                        "{%0,%1,%2,%3}, {%4,%5,%6,%7}, {%8,%9}, {%0,%1,%2,%3};"
                        : "+f"(acc[i][j][0]), "+f"(acc[i][j][1]),
                          "+f"(acc[i][j][2]), "+f"(acc[i][j][3])
                        : "r"(af[i][0]), "r"(af[i][1]), "r"(af[i][2]), "r"(af[i][3]),
                          "r"(bf[j][0]), "r"(bf[j][1]));
                }
        }
        __syncthreads();
    }

    // ---- fused LSTM epilogue ----
    // thread's n-block j: gate = j&3, colgroup cg = j>>2.
    // h-col = c0 + (2*(warp&3) + cg)*8 + 2*(lane&3)  (+1 for second reg)
    const float* bs = (const float*)(smem + SM_BIAS);
    const size_t oh_off = (size_t)B_DIM * H_DIM;
    const int colb = 2 * (warp & 3);
    const int lc2 = 2 * (lane & 3);

#pragma unroll
    for (int cg = 0; cg < 2; cg++) {
        const int jb = cg * 4;
        const int hc = c0 + (colb + cg) * 8 + lc2;       // global h-col (pair hc, hc+1)
        const int bcol = (colb + cg) * 8 + lc2;          // col within CTA's 64
        const float b_i0 = bs[0 * 64 + bcol], b_i1 = bs[0 * 64 + bcol + 1];
        const float b_f0 = bs[1 * 64 + bcol], b_f1 = bs[1 * 64 + bcol + 1];
        const float b_o0 = bs[2 * 64 + bcol], b_o1 = bs[2 * 64 + bcol + 1];
        const float b_g0 = bs[3 * 64 + bcol], b_g1 = bs[3 * 64 + bcol + 1];
#pragma unroll
        for (int i = 0; i < 4; i++) {
            const int rbase = m0 + wm + i * 16 + (lane >> 2);
#pragma unroll
            for (int t = 0; t < 2; t++) {
                const int row = rbase + t * 8;
                const int k0 = t * 2;
                float2 cp = *(const float2*)(c_prev + (size_t)row * 1024 + hc);

                float iv0 = acc[i][jb + 0][k0]     + b_i0;
                float iv1 = acc[i][jb + 0][k0 + 1] + b_i1;
                float fv0 = acc[i][jb + 1][k0]     + b_f0;
                float fv1 = acc[i][jb + 1][k0 + 1] + b_f1;
                float ov0 = acc[i][jb + 2][k0]     + b_o0;
                float ov1 = acc[i][jb + 2][k0 + 1] + b_o1;
                float gv0 = acc[i][jb + 3][k0]     + b_g0;
                float gv1 = acc[i][jb + 3][k0 + 1] + b_g1;

                float ig0 = 1.0f / (1.0f + expf(-iv0));
                float ig1 = 1.0f / (1.0f + expf(-iv1));
                float fg0 = 1.0f / (1.0f + expf(-fv0));
                float fg1 = 1.0f / (1.0f + expf(-fv1));
                float og0 = 1.0f / (1.0f + expf(-ov0));
                float og1 = 1.0f / (1.0f + expf(-ov1));
                float gg0 = tanhf(gv0);
                float gg1 = tanhf(gv1);

                float cv0 = fg0 * cp.x + ig0 * gg0;
                float cv1 = fg1 * cp.y + ig1 * gg1;
                float hv0 = og0 * tanhf(cv0);
                float hv1 = og1 * tanhf(cv1);

                *(float2*)(out + (size_t)row * 1024 + hc) = make_float2(cv0, cv1);
                *(float2*)(out + oh_off + (size_t)row * 1024 + hc) = make_float2(hv0, hv1);
            }
        }
    }
}

extern "C" void kernel_launch(void* const* d_in, const int* in_sizes, int n_in,
                              void* d_out, int out_size) {
    const float* x      = (const float*)d_in[0];
    const float* c_prev = (const float*)d_in[1];
    const float* h_prev = (const float*)d_in[2];
    const float* Wx     = (const float*)d_in[3];
    const float* bx     = (const float*)d_in[4];
    const float* Wh     = (const float*)d_in[5];
    const float* bh     = (const float*)d_in[6];
    float* out = (float*)d_out;

    cudaFuncSetAttribute(lstm_fused_kernel,
                         cudaFuncAttributeMaxDynamicSharedMemorySize, SMEM_TOTAL);
    dim3 grid(H_DIM / 64, B_DIM / BM);  // (16, 64) = 1024 CTAs
    lstm_fused_kernel<<<grid, 256, SMEM_TOTAL>>>(x, c_prev, h_prev, Wx, bx, Wh, bh, out);
}

// round 4
// speedup vs baseline: 1.1073x; 1.0366x over previous
#include <cuda_runtime.h>
#include <math.h>
#include <stdint.h>

// Fused LSTM cell, mma.sync tf32 (compute_103-safe).
// gates[B,4H] = x@Wx^T + h@Wh^T (+bias), pointwise fused in epilogue.
// CTA tile: M=128 x N=128 (4 gates x 32 h-cols, gate-interleaved), BK=32.
// 3-stage cp.async pipeline, ONE __syncthreads per k-tile, 2 CTAs/SM.

#define B_DIM 8192
#define H_DIM 1024
#define BM 128
#define BN 128
#define BK 32
#define PADK 36                            // floats per smem row
#define A_STAGE_BYTES (BM * PADK * 4)      // 18432
#define B_STAGE_BYTES (BN * PADK * 4)      // 18432
#define STAGE_BYTES   (A_STAGE_BYTES + B_STAGE_BYTES)  // 36864
#define STAGES 3
#define NSTG 64                            // 2048 / 32
#define SM_BIAS (STAGES * STAGE_BYTES)     // 110592
#define SMEM_TOTAL (SM_BIAS + 128 * 4)     // 111104  (2 CTAs = 222KB <= 227KB)

__device__ __forceinline__ uint32_t smem_u32(const void* p) {
    uint32_t a;
    asm("{ .reg .u64 t; cvta.to.shared.u64 t, %1; cvt.u32.u64 %0, t; }" : "=r"(a) : "l"(p));
    return a;
}
__device__ __forceinline__ void cp16(uint32_t dst, const void* src) {
    asm volatile("cp.async.cg.shared.global [%0], [%1], 16;" :: "r"(dst), "l"(src));
}

// B smem row r -> weight row: gate=(r>>3)&3, hcol = c0 + (r>>5)*8 + (r&7)
__device__ __forceinline__ void load_stage(
    uint32_t sb, int kt, int m0, int c0, int tid,
    const float* __restrict__ x, const float* __restrict__ h,
    const float* __restrict__ Wx, const float* __restrict__ Wh)
{
    const int k0 = kt * BK;
    const float* Asrc = (k0 < 1024) ? x : h;
    const float* Bsrc = (k0 < 1024) ? Wx : Wh;
    const int kc = k0 & 1023;
    const uint32_t abase = sb + (kt % STAGES) * STAGE_BYTES;
    const uint32_t bbase = abase + A_STAGE_BYTES;
#pragma unroll
    for (int p = 0; p < 4; p++) {          // A: 128 rows x 8 x 16B
        int ch = tid + p * 256;
        int row = ch >> 3, c16 = ch & 7;
        cp16(abase + row * (PADK * 4) + c16 * 16,
             Asrc + (size_t)(m0 + row) * 1024 + kc + c16 * 4);
    }
#pragma unroll
    for (int p = 0; p < 4; p++) {          // B: 128 rows x 8 x 16B
        int ch = tid + p * 256;
        int row = ch >> 3, c16 = ch & 7;
        int wrow = ((row >> 3) & 3) * 1024 + c0 + (row >> 5) * 8 + (row & 7);
        cp16(bbase + row * (PADK * 4) + c16 * 16,
             Bsrc + (size_t)wrow * 1024 + kc + c16 * 4);
    }
}

__global__ void __launch_bounds__(256, 2) lstm_fused_kernel(
    const float* __restrict__ x,      // [B,1024]
    const float* __restrict__ c_prev, // [B,1024]
    const float* __restrict__ h_prev, // [B,1024]
    const float* __restrict__ Wx,     // [4096,1024]
    const float* __restrict__ bx,     // [4096]
    const float* __restrict__ Wh,     // [4096,1024]
    const float* __restrict__ bh,     // [4096]
    float* __restrict__ out)          // [2*B*1024]: c then h
{
    extern __shared__ char smem[];
    const uint32_t sb = smem_u32(smem);
    const int tid = threadIdx.x;
    const int warp = tid >> 5, lane = tid & 31;
    const int wm = (warp >> 2) * 64;       // 0,64
    const int wn = (warp & 3) * 32;        // 0,32,64,96 (smem B rows)
    const int m0 = blockIdx.y * BM;
    const int c0 = blockIdx.x * 32;        // 32 h-cols per CTA

    if (tid < 128) {                        // bias sums: bs[g*32 + col]
        int g = tid >> 5, col = tid & 31;
        ((float*)(smem + SM_BIAS))[tid] = bx[g * 1024 + c0 + col] + bh[g * 1024 + c0 + col];
    }

    float acc[4][4][4];
#pragma unroll
    for (int i = 0; i < 4; i++)
#pragma unroll
        for (int j = 0; j < 4; j++)
#pragma unroll
            for (int r = 0; r < 4; r++) acc[i][j][r] = 0.f;

    load_stage(sb, 0, m0, c0, tid, x, h_prev, Wx, Wh);
    asm volatile("cp.async.commit_group;" ::: "memory");
    load_stage(sb, 1, m0, c0, tid, x, h_prev, Wx, Wh);
    asm volatile("cp.async.commit_group;" ::: "memory");

    for (int kt = 0; kt < NSTG; ++kt) {
        asm volatile("cp.async.wait_group 1;" ::: "memory");
        __syncthreads();
        // loads for kt+2 go into buffer (kt+2)%3 == (kt-1)%3; every warp past
        // this barrier has finished computing k-tile kt-1, so the buffer is free.
        if (kt + 2 < NSTG) {
            load_stage(sb, kt + 2, m0, c0, tid, x, h_prev, Wx, Wh);
            asm volatile("cp.async.commit_group;" ::: "memory");
        } else {
            asm volatile("cp.async.commit_group;" ::: "memory");  // keep count in step
        }

        const unsigned* As = (const unsigned*)(smem + (kt % STAGES) * STAGE_BYTES);
        const unsigned* Bs = (const unsigned*)(smem + (kt % STAGES) * STAGE_BYTES + A_STAGE_BYTES);

#pragma unroll
        for (int ks = 0; ks < 4; ++ks) {
            const int cA = ks * 8 + (lane & 3);
            unsigned af[4][4], bf[4][2];
#pragma unroll
            for (int i = 0; i < 4; i++) {
                int r0 = wm + i * 16 + (lane >> 2);
                af[i][0] = As[r0 * PADK + cA];
                af[i][1] = As[(r0 + 8) * PADK + cA];
                af[i][2] = As[r0 * PADK + cA + 4];
                af[i][3] = As[(r0 + 8) * PADK + cA + 4];
            }
#pragma unroll
            for (int j = 0; j < 4; j++) {
                int n0 = wn + j * 8 + (lane >> 2);
                bf[j][0] = Bs[n0 * PADK + cA];
                bf[j][1] = Bs[n0 * PADK + cA + 4];
            }
#pragma unroll
            for (int i = 0; i < 4; i++)
#pragma unroll
                for (int j = 0; j < 4; j++) {
                    asm volatile(
                        "mma.sync.aligned.m16n8k8.row.col.f32.tf32.tf32.f32 "
                        "{%0,%1,%2,%3}, {%4,%5,%6,%7}, {%8,%9}, {%0,%1,%2,%3};"
                        : "+f"(acc[i][j][0]), "+f"(acc[i][j][1]),
                          "+f"(acc[i][j][2]), "+f"(acc[i][j][3])
                        : "r"(af[i][0]), "r"(af[i][1]), "r"(af[i][2]), "r"(af[i][3]),
                          "r"(bf[j][0]), "r"(bf[j][1]));
                }
        }
    }

    // ---- fused LSTM epilogue ----
    // j = gate. h-col pair: hc = c0 + (warp&3)*8 + 2*(lane&3)
    const float* bs = (const float*)(smem + SM_BIAS);
    const size_t oh_off = (size_t)B_DIM * H_DIM;
    const int bcol = (warp & 3) * 8 + 2 * (lane & 3);
    const int hc = c0 + bcol;

    const float b_i0 = bs[0 * 32 + bcol], b_i1 = bs[0 * 32 + bcol + 1];
    const float b_f0 = bs[1 * 32 + bcol], b_f1 = bs[1 * 32 + bcol + 1];
    const float b_o0 = bs[2 * 32 + bcol], b_o1 = bs[2 * 32 + bcol + 1];
    const float b_g0 = bs[3 * 32 + bcol], b_g1 = bs[3 * 32 + bcol + 1];

#pragma unroll
    for (int i = 0; i < 4; i++) {
        const int rbase = m0 + wm + i * 16 + (lane >> 2);
#pragma unroll
        for (int t = 0; t < 2; t++) {
            const int row = rbase + t * 8;
            const int k0 = t * 2;
            float2 cp = *(const float2*)(c_prev + (size_t)row * 1024 + hc);

            float iv0 = acc[i][0][k0]     + b_i0;
            float iv1 = acc[i][0][k0 + 1] + b_i1;
            float fv0 = acc[i][1][k0]     + b_f0;
            float fv1 = acc[i][1][k0 + 1] + b_f1;
            float ov0 = acc[i][2][k0]     + b_o0;
            float ov1 = acc[i][2][k0 + 1] + b_o1;
            float gv0 = acc[i][3][k0]     + b_g0;
            float gv1 = acc[i][3][k0 + 1] + b_g1;

            float ig0 = 1.0f / (1.0f + expf(-iv0));
            float ig1 = 1.0f / (1.0f + expf(-iv1));
            float fg0 = 1.0f / (1.0f + expf(-fv0));
            float fg1 = 1.0f / (1.0f + expf(-fv1));
            float og0 = 1.0f / (1.0f + expf(-ov0));
            float og1 = 1.0f / (1.0f + expf(-ov1));
            float gg0 = tanhf(gv0);
            float gg1 = tanhf(gv1);

            float cv0 = fg0 * cp.x + ig0 * gg0;
            float cv1 = fg1 * cp.y + ig1 * gg1;
            float hv0 = og0 * tanhf(cv0);
            float hv1 = og1 * tanhf(cv1);

            *(float2*)(out + (size_t)row * 1024 + hc) = make_float2(cv0, cv1);
            *(float2*)(out + oh_off + (size_t)row * 1024 + hc) = make_float2(hv0, hv1);
        }
    }
}

extern "C" void kernel_launch(void* const* d_in, const int* in_sizes, int n_in,
                              void* d_out, int out_size) {
    const float* x      = (const float*)d_in[0];
    const float* c_prev = (const float*)d_in[1];
    const float* h_prev = (const float*)d_in[2];
    const float* Wx     = (const float*)d_in[3];
    const float* bx     = (const float*)d_in[4];
    const float* Wh     = (const float*)d_in[5];
    const float* bh     = (const float*)d_in[6];
    float* out = (float*)d_out;

    cudaFuncSetAttribute(lstm_fused_kernel,
                         cudaFuncAttributeMaxDynamicSharedMemorySize, SMEM_TOTAL);
    dim3 grid(H_DIM / 32, B_DIM / BM);  // (32, 64) = 2048 CTAs
    lstm_fused_kernel<<<grid, 256, SMEM_TOTAL>>>(x, c_prev, h_prev, Wx, bx, Wh, bh, out);
}

// round 5
// speedup vs baseline: 2.6104x; 2.3574x over previous
#include <cuda_runtime.h>
#include <cuda_fp16.h>
#include <math.h>
#include <stdint.h>

// Fused LSTM cell, fp16 mma.sync m16n8k16 (same 10-bit mantissa as tf32, 2x K
// per HMMA) + ldmatrix fragment loads.
// Pass 0: convert x|h -> A16[8192x2048], Wx|Wh -> B16[4096x2048] (RN).
// Pass 1: GEMM gates = A16 @ B16^T, CTA tile M=128 x N=128 (4 gates x 32
//         h-cols, gate-interleaved), BK=64, 3-stage cp.async, fused LSTM epi.

#define B_DIM 8192
#define H_DIM 1024
#define KTOT  2048
#define BM 128
#define BK 64                                  // halves per stage-row (128B)
#define A_STAGE 16384
#define B_STAGE 16384
#define STAGE_BYTES (A_STAGE + B_STAGE)        // 32768
#define STAGES 3
#define NSTG (KTOT / BK)                       // 32
#define SM_BIAS (STAGES * STAGE_BYTES)         // 98304
#define SMEM_TOTAL (SM_BIAS + 128 * 4)         // 98816 (2 CTAs/SM fits 227KB)

__device__ __align__(128) __half A16[(size_t)B_DIM * KTOT];   // 32 MB
__device__ __align__(128) __half B16[(size_t)4096 * KTOT];    // 16 MB

__device__ __forceinline__ uint32_t smem_u32(const void* p) {
    uint32_t a;
    asm("{ .reg .u64 t; cvta.to.shared.u64 t, %1; cvt.u32.u64 %0, t; }" : "=r"(a) : "l"(p));
    return a;
}
__device__ __forceinline__ void cp16(uint32_t dst, const void* src) {
    asm volatile("cp.async.cg.shared.global [%0], [%1], 16;" :: "r"(dst), "l"(src));
}
__device__ __forceinline__ uint32_t h2u(__half2 h) {
    return *reinterpret_cast<uint32_t*>(&h);
}

// ---------------- Pass 0: fp32 -> fp16 conversion (K-concatenated) ----------
__global__ void __launch_bounds__(256) cvt_kernel(
    const float* __restrict__ x, const float* __restrict__ hp,
    const float* __restrict__ Wx, const float* __restrict__ Wh)
{
    size_t t = (size_t)blockIdx.x * 256 + threadIdx.x;
    const size_t NA = (size_t)B_DIM * KTOT / 8;   // 2M chunks of 8
    const float* src;
    __half* dst;
    if (t < NA) {
        size_t e = t * 8;
        int b = (int)(e >> 11), k = (int)(e & 2047);
        src = (k < 1024) ? x + (size_t)b * 1024 + k
                         : hp + (size_t)b * 1024 + (k - 1024);
        dst = A16 + e;
    } else {
        size_t e = (t - NA) * 8;
        int n = (int)(e >> 11), k = (int)(e & 2047);
        src = (k < 1024) ? Wx + (size_t)n * 1024 + k
                         : Wh + (size_t)n * 1024 + (k - 1024);
        dst = B16 + e;
    }
    float4 v0 = *(const float4*)src;
    float4 v1 = *(const float4*)(src + 4);
    uint4 u;
    u.x = h2u(__floats2half2_rn(v0.x, v0.y));
    u.y = h2u(__floats2half2_rn(v0.z, v0.w));
    u.z = h2u(__floats2half2_rn(v1.x, v1.y));
    u.w = h2u(__floats2half2_rn(v1.z, v1.w));
    *(uint4*)dst = u;
}

// ---------------- Pass 1: GEMM + fused LSTM --------------------------------
// B smem row r -> weight row: gate=(r>>3)&3, hcol = c0 + (r>>5)*8 + (r&7)
__device__ __forceinline__ void load_stage(uint32_t sb, int kt, int m0, int c0, int tid)
{
    const int k0 = kt * BK;                     // halves
    const uint32_t abase = sb + (kt % STAGES) * STAGE_BYTES;
    const uint32_t bbase = abase + A_STAGE;
#pragma unroll
    for (int p = 0; p < 4; p++) {               // A: 128 rows x 8 x 16B
        int ch = tid + p * 256;
        int row = ch >> 3, c = ch & 7;
        cp16(abase + row * 128 + ((c ^ (row & 7)) << 4),
             A16 + (size_t)(m0 + row) * KTOT + k0 + c * 8);
    }
#pragma unroll
    for (int p = 0; p < 4; p++) {               // B: 128 rows x 8 x 16B
        int ch = tid + p * 256;
        int row = ch >> 3, c = ch & 7;
        int wrow = ((row >> 3) & 3) * 1024 + c0 + (row >> 5) * 8 + (row & 7);
        cp16(bbase + row * 128 + ((c ^ (row & 7)) << 4),
             B16 + (size_t)wrow * KTOT + k0 + c * 8);
    }
}

__global__ void __launch_bounds__(256, 2) lstm_fused_kernel(
    const float* __restrict__ c_prev,  // [B,1024]
    const float* __restrict__ bx,      // [4096]
    const float* __restrict__ bh,      // [4096]
    float* __restrict__ out)           // [2*B*1024]: c then h
{
    extern __shared__ char smem[];
    const uint32_t sb = smem_u32(smem);
    const int tid = threadIdx.x;
    const int warp = tid >> 5, lane = tid & 31;
    const int wm = (warp >> 2) * 64;            // 0,64
    const int wn = (warp & 3) * 32;             // 0,32,64,96
    const int m0 = blockIdx.y * BM;
    const int c0 = blockIdx.x * 32;

    if (tid < 128) {
        int g = tid >> 5, col = tid & 31;
        ((float*)(smem + SM_BIAS))[tid] = bx[g * 1024 + c0 + col] + bh[g * 1024 + c0 + col];
    }

    float acc[4][4][4];
#pragma unroll
    for (int i = 0; i < 4; i++)
#pragma unroll
        for (int j = 0; j < 4; j++)
#pragma unroll
            for (int r = 0; r < 4; r++) acc[i][j][r] = 0.f;

    load_stage(sb, 0, m0, c0, tid);
    asm volatile("cp.async.commit_group;" ::: "memory");
    load_stage(sb, 1, m0, c0, tid);
    asm volatile("cp.async.commit_group;" ::: "memory");

    // precomputed lane pieces for ldmatrix addressing
    const int a_row = ((lane >> 3) & 1) * 8 + (lane & 7);   // + wm + i*16
    const int a_kh  = lane >> 4;                            // k-half select
    const int b_row = ((lane >> 4) & 1) * 8 + (lane & 7);   // + wn + jp*16
    const int b_kh  = (lane >> 3) & 1;

    for (int kt = 0; kt < NSTG; ++kt) {
        asm volatile("cp.async.wait_group 1;" ::: "memory");
        __syncthreads();
        if (kt + 2 < NSTG) {
            load_stage(sb, kt + 2, m0, c0, tid);
            asm volatile("cp.async.commit_group;" ::: "memory");
        } else {
            asm volatile("cp.async.commit_group;" ::: "memory");
        }

        const uint32_t abuf = sb + (kt % STAGES) * STAGE_BYTES;
        const uint32_t bbuf = abuf + A_STAGE;

#pragma unroll
        for (int ks = 0; ks < 4; ++ks) {
            uint32_t af[4][4], bf[4][2];
#pragma unroll
            for (int i = 0; i < 4; i++) {
                int ra = wm + i * 16 + a_row;
                int ck = ks * 2 + a_kh;
                uint32_t addr = abuf + ra * 128 + (((uint32_t)(ck ^ (ra & 7))) << 4);
                asm volatile(
                    "ldmatrix.sync.aligned.m8n8.x4.shared.b16 {%0,%1,%2,%3}, [%4];"
                    : "=r"(af[i][0]), "=r"(af[i][1]), "=r"(af[i][2]), "=r"(af[i][3])
                    : "r"(addr));
            }
#pragma unroll
            for (int jp = 0; jp < 2; jp++) {
                int rn = wn + jp * 16 + b_row;
                int ck = ks * 2 + b_kh;
                uint32_t addr = bbuf + rn * 128 + (((uint32_t)(ck ^ (rn & 7))) << 4);
                asm volatile(
                    "ldmatrix.sync.aligned.m8n8.x4.shared.b16 {%0,%1,%2,%3}, [%4];"
                    : "=r"(bf[2 * jp][0]), "=r"(bf[2 * jp][1]),
                      "=r"(bf[2 * jp + 1][0]), "=r"(bf[2 * jp + 1][1])
                    : "r"(addr));
            }
#pragma unroll
            for (int i = 0; i < 4; i++)
#pragma unroll
                for (int j = 0; j < 4; j++) {
                    asm volatile(
                        "mma.sync.aligned.m16n8k16.row.col.f32.f16.f16.f32 "
                        "{%0,%1,%2,%3}, {%4,%5,%6,%7}, {%8,%9}, {%0,%1,%2,%3};"
                        : "+f"(acc[i][j][0]), "+f"(acc[i][j][1]),
                          "+f"(acc[i][j][2]), "+f"(acc[i][j][3])
                        : "r"(af[i][0]), "r"(af[i][1]), "r"(af[i][2]), "r"(af[i][3]),
                          "r"(bf[j][0]), "r"(bf[j][1]));
                }
        }
    }

    // ---- fused LSTM epilogue ----
    const float* bs = (const float*)(smem + SM_BIAS);
    const size_t oh_off = (size_t)B_DIM * H_DIM;
    const int bcol = (warp & 3) * 8 + 2 * (lane & 3);
    const int hc = c0 + bcol;

    const float b_i0 = bs[0 * 32 + bcol], b_i1 = bs[0 * 32 + bcol + 1];
    const float b_f0 = bs[1 * 32 + bcol], b_f1 = bs[1 * 32 + bcol + 1];
    const float b_o0 = bs[2 * 32 + bcol], b_o1 = bs[2 * 32 + bcol + 1];
    const float b_g0 = bs[3 * 32 + bcol], b_g1 = bs[3 * 32 + bcol + 1];

#pragma unroll
    for (int i = 0; i < 4; i++) {
        const int rbase = m0 + wm + i * 16 + (lane >> 2);
#pragma unroll
        for (int t = 0; t < 2; t++) {
            const int row = rbase + t * 8;
            const int k0 = t * 2;
            float2 cp = *(const float2*)(c_prev + (size_t)row * 1024 + hc);

            float iv0 = acc[i][0][k0]     + b_i0;
            float iv1 = acc[i][0][k0 + 1] + b_i1;
            float fv0 = acc[i][1][k0]     + b_f0;
            float fv1 = acc[i][1][k0 + 1] + b_f1;
            float ov0 = acc[i][2][k0]     + b_o0;
            float ov1 = acc[i][2][k0 + 1] + b_o1;
            float gv0 = acc[i][3][k0]     + b_g0;
            float gv1 = acc[i][3][k0 + 1] + b_g1;

            float ig0 = 1.0f / (1.0f + expf(-iv0));
            float ig1 = 1.0f / (1.0f + expf(-iv1));
            float fg0 = 1.0f / (1.0f + expf(-fv0));
            float fg1 = 1.0f / (1.0f + expf(-fv1));
            float og0 = 1.0f / (1.0f + expf(-ov0));
            float og1 = 1.0f / (1.0f + expf(-ov1));
            float gg0 = tanhf(gv0);
            float gg1 = tanhf(gv1);

            float cv0 = fg0 * cp.x + ig0 * gg0;
            float cv1 = fg1 * cp.y + ig1 * gg1;
            float hv0 = og0 * tanhf(cv0);
            float hv1 = og1 * tanhf(cv1);

            *(float2*)(out + (size_t)row * 1024 + hc) = make_float2(cv0, cv1);
            *(float2*)(out + oh_off + (size_t)row * 1024 + hc) = make_float2(hv0, hv1);
        }
    }
}

extern "C" void kernel_launch(void* const* d_in, const int* in_sizes, int n_in,
                              void* d_out, int out_size) {
    const float* x      = (const float*)d_in[0];
    const float* c_prev = (const float*)d_in[1];
    const float* h_prev = (const float*)d_in[2];
    const float* Wx     = (const float*)d_in[3];
    const float* bx     = (const float*)d_in[4];
    const float* Wh     = (const float*)d_in[5];
    const float* bh     = (const float*)d_in[6];
    float* out = (float*)d_out;

    // Pass 0: 25,165,824 halves / 8 per thread = 3,145,728 threads
    cvt_kernel<<<12288, 256>>>(x, h_prev, Wx, Wh);

    cudaFuncSetAttribute(lstm_fused_kernel,
                         cudaFuncAttributeMaxDynamicSharedMemorySize, SMEM_TOTAL);
    dim3 grid(H_DIM / 32, B_DIM / BM);  // (32, 64) = 2048 CTAs
    lstm_fused_kernel<<<grid, 256, SMEM_TOTAL>>>(c_prev, bx, bh, out);
}

// round 6
// speedup vs baseline: 2.8303x; 1.0842x over previous
#include <cuda_runtime.h>
#include <cuda_fp16.h>
#include <math.h>
#include <stdint.h>

// Fused LSTM cell, fp16 mma.sync m16n8k16 + ldmatrix.
// Pass 0: convert x|h -> A16[8192x2048], Wx|Wh -> B16[4096x2048] (RN).
// Pass 1: GEMM gates = A16 @ B16^T, CTA tile M=128 x N=128 (4 gates x 32
//         h-cols, gate-interleaved), BK=64, 3-stage cp.async, fused LSTM epi.
// R6: kt unrolled by 3 (compile-time buffer), cp.async interleaved into ks
//     stream to shrink the post-barrier tensor bubble.

#define B_DIM 8192
#define H_DIM 1024
#define KTOT  2048
#define BM 128
#define BK 64
#define A_STAGE 16384
#define B_STAGE 16384
#define STAGE_BYTES (A_STAGE + B_STAGE)        // 32768
#define STAGES 3
#define NSTG (KTOT / BK)                       // 32
#define SM_BIAS (STAGES * STAGE_BYTES)         // 98304
#define SMEM_TOTAL (SM_BIAS + 128 * 4)         // 98816

__device__ __align__(128) __half A16[(size_t)B_DIM * KTOT];   // 32 MB
__device__ __align__(128) __half B16[(size_t)4096 * KTOT];    // 16 MB

__device__ __forceinline__ uint32_t smem_u32(const void* p) {
    uint32_t a;
    asm("{ .reg .u64 t; cvta.to.shared.u64 t, %1; cvt.u32.u64 %0, t; }" : "=r"(a) : "l"(p));
    return a;
}
__device__ __forceinline__ void cp16(uint32_t dst, const void* src) {
    asm volatile("cp.async.cg.shared.global [%0], [%1], 16;" :: "r"(dst), "l"(src));
}
__device__ __forceinline__ uint32_t h2u(__half2 h) {
    return *reinterpret_cast<uint32_t*>(&h);
}

// ---------------- Pass 0: fp32 -> fp16 conversion (K-concatenated) ----------
__global__ void __launch_bounds__(256) cvt_kernel(
    const float* __restrict__ x, const float* __restrict__ hp,
    const float* __restrict__ Wx, const float* __restrict__ Wh)
{
    size_t t = (size_t)blockIdx.x * 256 + threadIdx.x;
    const size_t NA = (size_t)B_DIM * KTOT / 8;
    const float* src;
    __half* dst;
    if (t < NA) {
        size_t e = t * 8;
        int b = (int)(e >> 11), k = (int)(e & 2047);
        src = (k < 1024) ? x + (size_t)b * 1024 + k
                         : hp + (size_t)b * 1024 + (k - 1024);
        dst = A16 + e;
    } else {
        size_t e = (t - NA) * 8;
        int n = (int)(e >> 11), k = (int)(e & 2047);
        src = (k < 1024) ? Wx + (size_t)n * 1024 + k
                         : Wh + (size_t)n * 1024 + (k - 1024);
        dst = B16 + e;
    }
    float4 v0 = *(const float4*)src;
    float4 v1 = *(const float4*)(src + 4);
    uint4 u;
    u.x = h2u(__floats2half2_rn(v0.x, v0.y));
    u.y = h2u(__floats2half2_rn(v0.z, v0.w));
    u.z = h2u(__floats2half2_rn(v1.x, v1.y));
    u.w = h2u(__floats2half2_rn(v1.z, v1.w));
    *(uint4*)dst = u;
}

// ---------------- Pass 1: GEMM + fused LSTM --------------------------------
struct TileCtx {
    uint32_t sb;
    int m0, c0, tid;
    int wm, wn;
    int a_row, a_kh, b_row, b_kh;
    float (*acc)[4][4];
};

template <int LBUF>
__device__ __forceinline__ void issue_loads_A(const TileCtx& t, int kt) {
    const int k0 = kt * BK;
    const uint32_t abase = t.sb + LBUF * STAGE_BYTES;
#pragma unroll
    for (int p = 0; p < 4; p++) {
        int ch = t.tid + p * 256;
        int row = ch >> 3, c = ch & 7;
        cp16(abase + row * 128 + ((c ^ (row & 7)) << 4),
             A16 + (size_t)(t.m0 + row) * KTOT + k0 + c * 8);
    }
}
template <int LBUF>
__device__ __forceinline__ void issue_loads_B(const TileCtx& t, int kt) {
    const int k0 = kt * BK;
    const uint32_t bbase = t.sb + LBUF * STAGE_BYTES + A_STAGE;
#pragma unroll
    for (int p = 0; p < 4; p++) {
        int ch = t.tid + p * 256;
        int row = ch >> 3, c = ch & 7;
        int wrow = ((row >> 3) & 3) * 1024 + t.c0 + (row >> 5) * 8 + (row & 7);
        cp16(bbase + row * 128 + ((c ^ (row & 7)) << 4),
             B16 + (size_t)wrow * KTOT + k0 + c * 8);
    }
}

template <int BUF>
__device__ __forceinline__ void compute_ks(const TileCtx& t, int ks) {
    const uint32_t abuf = t.sb + BUF * STAGE_BYTES;
    const uint32_t bbuf = abuf + A_STAGE;
    uint32_t af[4][4], bf[4][2];
#pragma unroll
    for (int i = 0; i < 4; i++) {
        int ra = t.wm + i * 16 + t.a_row;
        int ck = ks * 2 + t.a_kh;
        uint32_t addr = abuf + ra * 128 + (((uint32_t)(ck ^ (ra & 7))) << 4);
        asm volatile(
            "ldmatrix.sync.aligned.m8n8.x4.shared.b16 {%0,%1,%2,%3}, [%4];"
            : "=r"(af[i][0]), "=r"(af[i][1]), "=r"(af[i][2]), "=r"(af[i][3])
            : "r"(addr));
    }
#pragma unroll
    for (int jp = 0; jp < 2; jp++) {
        int rn = t.wn + jp * 16 + t.b_row;
        int ck = ks * 2 + t.b_kh;
        uint32_t addr = bbuf + rn * 128 + (((uint32_t)(ck ^ (rn & 7))) << 4);
        asm volatile(
            "ldmatrix.sync.aligned.m8n8.x4.shared.b16 {%0,%1,%2,%3}, [%4];"
            : "=r"(bf[2 * jp][0]), "=r"(bf[2 * jp][1]),
              "=r"(bf[2 * jp + 1][0]), "=r"(bf[2 * jp + 1][1])
            : "r"(addr));
    }
#pragma unroll
    for (int i = 0; i < 4; i++)
#pragma unroll
        for (int j = 0; j < 4; j++) {
            asm volatile(
                "mma.sync.aligned.m16n8k16.row.col.f32.f16.f16.f32 "
                "{%0,%1,%2,%3}, {%4,%5,%6,%7}, {%8,%9}, {%0,%1,%2,%3};"
                : "+f"(t.acc[i][j][0]), "+f"(t.acc[i][j][1]),
                  "+f"(t.acc[i][j][2]), "+f"(t.acc[i][j][3])
                : "r"(af[i][0]), "r"(af[i][1]), "r"(af[i][2]), "r"(af[i][3]),
                  "r"(bf[j][0]), "r"(bf[j][1]));
        }
}

template <int BUF, bool LOAD>
__device__ __forceinline__ void tile_step(const TileCtx& t, int kt) {
    constexpr int LBUF = (BUF + 2) % 3;
    asm volatile("cp.async.wait_group 1;" ::: "memory");
    __syncthreads();
    compute_ks<BUF>(t, 0);
    if (LOAD) issue_loads_A<LBUF>(t, kt + 2);
    compute_ks<BUF>(t, 1);
    if (LOAD) issue_loads_B<LBUF>(t, kt + 2);
    asm volatile("cp.async.commit_group;" ::: "memory");
    compute_ks<BUF>(t, 2);
    compute_ks<BUF>(t, 3);
}

__global__ void __launch_bounds__(256, 2) lstm_fused_kernel(
    const float* __restrict__ c_prev,
    const float* __restrict__ bx,
    const float* __restrict__ bh,
    float* __restrict__ out)
{
    extern __shared__ char smem[];
    const uint32_t sb = smem_u32(smem);
    const int tid = threadIdx.x;
    const int warp = tid >> 5, lane = tid & 31;

    TileCtx t;
    t.sb = sb;
    t.tid = tid;
    t.wm = (warp >> 2) * 64;
    t.wn = (warp & 3) * 32;
    t.m0 = blockIdx.y * BM;
    t.c0 = blockIdx.x * 32;
    t.a_row = ((lane >> 3) & 1) * 8 + (lane & 7);
    t.a_kh  = lane >> 4;
    t.b_row = ((lane >> 4) & 1) * 8 + (lane & 7);
    t.b_kh  = (lane >> 3) & 1;

    if (tid < 128) {
        int g = tid >> 5, col = tid & 31;
        ((float*)(smem + SM_BIAS))[tid] =
            bx[g * 1024 + t.c0 + col] + bh[g * 1024 + t.c0 + col];
    }

    float acc[4][4][4];
#pragma unroll
    for (int i = 0; i < 4; i++)
#pragma unroll
        for (int j = 0; j < 4; j++)
#pragma unroll
            for (int r = 0; r < 4; r++) acc[i][j][r] = 0.f;
    t.acc = acc;

    issue_loads_A<0>(t, 0);
    issue_loads_B<0>(t, 0);
    asm volatile("cp.async.commit_group;" ::: "memory");
    issue_loads_A<1>(t, 1);
    issue_loads_B<1>(t, 1);
    asm volatile("cp.async.commit_group;" ::: "memory");

    // kt = 0..29 unrolled by 3 with loads; 30,31 tail without.
    for (int kt = 0; kt < 30; kt += 3) {
        tile_step<0, true>(t, kt);
        tile_step<1, true>(t, kt + 1);
        tile_step<2, true>(t, kt + 2);
    }
    // tail: keep group count in step with empty commits
    {
        asm volatile("cp.async.wait_group 1;" ::: "memory");
        __syncthreads();
        asm volatile("cp.async.commit_group;" ::: "memory");
        compute_ks<0>(t, 0); compute_ks<0>(t, 1);
        compute_ks<0>(t, 2); compute_ks<0>(t, 3);

        asm volatile("cp.async.wait_group 1;" ::: "memory");
        __syncthreads();
        compute_ks<1>(t, 0); compute_ks<1>(t, 1);
        compute_ks<1>(t, 2); compute_ks<1>(t, 3);
    }

    // ---- fused LSTM epilogue ----
    const float* bs = (const float*)(smem + SM_BIAS);
    const size_t oh_off = (size_t)B_DIM * H_DIM;
    const int bcol = (warp & 3) * 8 + 2 * (lane & 3);
    const int hc = t.c0 + bcol;

    const float b_i0 = bs[0 * 32 + bcol], b_i1 = bs[0 * 32 + bcol + 1];
    const float b_f0 = bs[1 * 32 + bcol], b_f1 = bs[1 * 32 + bcol + 1];
    const float b_o0 = bs[2 * 32 + bcol], b_o1 = bs[2 * 32 + bcol + 1];
    const float b_g0 = bs[3 * 32 + bcol], b_g1 = bs[3 * 32 + bcol + 1];

#pragma unroll
    for (int i = 0; i < 4; i++) {
        const int rbase = t.m0 + t.wm + i * 16 + (lane >> 2);
#pragma unroll
        for (int tt = 0; tt < 2; tt++) {
            const int row = rbase + tt * 8;
            const int k0 = tt * 2;
            float2 cp = *(const float2*)(c_prev + (size_t)row * 1024 + hc);

            float iv0 = acc[i][0][k0]     + b_i0;
            float iv1 = acc[i][0][k0 + 1] + b_i1;
            float fv0 = acc[i][1][k0]     + b_f0;
            float fv1 = acc[i][1][k0 + 1] + b_f1;
            float ov0 = acc[i][2][k0]     + b_o0;
            float ov1 = acc[i][2][k0 + 1] + b_o1;
            float gv0 = acc[i][3][k0]     + b_g0;
            float gv1 = acc[i][3][k0 + 1] + b_g1;

            float ig0 = 1.0f / (1.0f + expf(-iv0));
            float ig1 = 1.0f / (1.0f + expf(-iv1));
            float fg0 = 1.0f / (1.0f + expf(-fv0));
            float fg1 = 1.0f / (1.0f + expf(-fv1));
            float og0 = 1.0f / (1.0f + expf(-ov0));
            float og1 = 1.0f / (1.0f + expf(-ov1));
            float gg0 = tanhf(gv0);
            float gg1 = tanhf(gv1);

            float cv0 = fg0 * cp.x + ig0 * gg0;
            float cv1 = fg1 * cp.y + ig1 * gg1;
            float hv0 = og0 * tanhf(cv0);
            float hv1 = og1 * tanhf(cv1);

            *(float2*)(out + (size_t)row * 1024 + hc) = make_float2(cv0, cv1);
            *(float2*)(out + oh_off + (size_t)row * 1024 + hc) = make_float2(hv0, hv1);
        }
    }
}

extern "C" void kernel_launch(void* const* d_in, const int* in_sizes, int n_in,
                              void* d_out, int out_size) {
    const float* x      = (const float*)d_in[0];
    const float* c_prev = (const float*)d_in[1];
    const float* h_prev = (const float*)d_in[2];
    const float* Wx     = (const float*)d_in[3];
    const float* bx     = (const float*)d_in[4];
    const float* Wh     = (const float*)d_in[5];
    const float* bh     = (const float*)d_in[6];
    float* out = (float*)d_out;

    cvt_kernel<<<12288, 256>>>(x, h_prev, Wx, Wh);

    cudaFuncSetAttribute(lstm_fused_kernel,
                         cudaFuncAttributeMaxDynamicSharedMemorySize, SMEM_TOTAL);
    dim3 grid(H_DIM / 32, B_DIM / BM);  // (32, 64)
    lstm_fused_kernel<<<grid, 256, SMEM_TOTAL>>>(c_prev, bx, bh, out);
}